// round 17
// baseline (speedup 1.0000x reference)
#include <cuda_runtime.h>
#include <cuda_fp16.h>
#include <mma.h>
#include <math.h>

using namespace nvcuda;

#define N_NODES 50000
#define E_EDGES 800000
#define IN_DIM  256
#define HID     128
#define OUT_DIM 16

#define SCAN_TPB 256
#define SCAN_BLOCKS ((N_NODES + SCAN_TPB - 1) / SCAN_TPB)   // 196
#define GEMM_BLOCKS ((N_NODES + 127) / 128)                  // 391
#define FILL_BLOCKS ((E_EDGES + 255) / 256)                  // 3125

// ---------------- scratch (device globals; allocation-free) ----------------
__device__ float   g_dinv[N_NODES];
__device__ int     g_cnt [N_NODES];
__device__ int     g_off [N_NODES + 1];
__device__ int     g_cur [N_NODES];
__device__ int     g_bsum[SCAN_BLOCKS];
__device__ float2  g_edge[E_EDGES];            // (src-bits, norm) per CSR slot
__device__ __half2 g_xw  [N_NODES * (HID/2)];  // messages, fp16 packed
__device__ float   g_h1  [N_NODES * HID];      // layer-1 activations (fp32)

__device__ __forceinline__ int clampN(int i) {
    i = i < 0 ? 0 : i;
    return i >= N_NODES ? N_NODES - 1 : i;
}

// ---------------- CSR build ----------------
__global__ void k_init() {
    int i = blockIdx.x * blockDim.x + threadIdx.x;
    if (i < N_NODES) g_cnt[i] = 0;
}

__global__ void k_count(const int* __restrict__ ei) {
    int e = blockIdx.x * blockDim.x + threadIdx.x;
    if (e < E_EDGES) atomicAdd(&g_cnt[clampN(ei[E_EDGES + e])], 1);
}

__global__ void k_dinv() {
    int i = blockIdx.x * blockDim.x + threadIdx.x;
    if (i < N_NODES) g_dinv[i] = rsqrtf((float)(g_cnt[i] + 1));
}

__global__ void __launch_bounds__(SCAN_TPB) k_scan1() {
    __shared__ int sh[SCAN_TPB];
    int t = threadIdx.x;
    int i = blockIdx.x * SCAN_TPB + t;
    int v = (i < N_NODES) ? g_cnt[i] : 0;
    sh[t] = v;
    __syncthreads();
#pragma unroll
    for (int d = 1; d < SCAN_TPB; d <<= 1) {
        int add = (t >= d) ? sh[t - d] : 0;
        __syncthreads();
        sh[t] += add;
        __syncthreads();
    }
    if (i < N_NODES) g_off[i] = sh[t] - v;
    if (t == SCAN_TPB - 1) g_bsum[blockIdx.x] = sh[t];
}

__global__ void __launch_bounds__(SCAN_TPB) k_scan2() {
    __shared__ int sh[SCAN_TPB];
    int t = threadIdx.x;
    int v = (t < SCAN_BLOCKS) ? g_bsum[t] : 0;
    sh[t] = v;
    __syncthreads();
#pragma unroll
    for (int d = 1; d < SCAN_TPB; d <<= 1) {
        int add = (t >= d) ? sh[t - d] : 0;
        __syncthreads();
        sh[t] += add;
        __syncthreads();
    }
    if (t < SCAN_BLOCKS) g_bsum[t] = sh[t] - v;
}

__global__ void __launch_bounds__(SCAN_TPB) k_scan3() {
    int i = blockIdx.x * SCAN_TPB + threadIdx.x;
    if (i < N_NODES) {
        int o = g_off[i] + g_bsum[blockIdx.x];
        g_off[i] = o;
        g_cur[i] = o;
    }
    if (i == 0) g_off[N_NODES] = E_EDGES;
}

// ---------------- GEMM body (wmma fp16, unchanged from 166us kernel) ------
#define KT 32
#define A_LD 40
#define B_LD 136

template <int K>
__device__ __forceinline__
void gemm_body(const float* __restrict__ X, const float* __restrict__ W) {
    __shared__ __align__(16) __half As[2][128][A_LD]; // [buf][m][k]
    __shared__ __align__(16) __half Bs[2][KT][B_LD];  // [buf][k][n]
    __shared__ float Cst[8][16][20];                  // epilogue staging

    const int tid = threadIdx.x;
    const int wid = tid >> 5;
    const int lane = tid & 31;
    const int wm = wid >> 1;
    const int wn = wid & 1;
    const int rowBase = blockIdx.x * 128;

    const int am = tid >> 1;
    const int ak = (tid & 1) * 16;
    const int gr = rowBase + am;
    const int bk = tid >> 3;
    const int bn = (tid & 7) * 16;

    wmma::fragment<wmma::accumulator, 16, 16, 16, float> fc[2][4];
#pragma unroll
    for (int i = 0; i < 2; i++)
#pragma unroll
        for (int j = 0; j < 4; j++) wmma::fill_fragment(fc[i][j], 0.0f);

    const int NT = K / KT;
    float4 a0, a1, a2, a3, b0, b1, b2, b3;

    {
        a0 = a1 = a2 = a3 = make_float4(0.f, 0.f, 0.f, 0.f);
        if (gr < N_NODES) {
            const float* xp = &X[(long long)gr * K + ak];
            a0 = *(const float4*)(xp);
            a1 = *(const float4*)(xp + 4);
            a2 = *(const float4*)(xp + 8);
            a3 = *(const float4*)(xp + 12);
        }
        const float* wp = &W[bk * HID + bn];
        b0 = *(const float4*)(wp);
        b1 = *(const float4*)(wp + 4);
        b2 = *(const float4*)(wp + 8);
        b3 = *(const float4*)(wp + 12);
        __half2 ah[8] = {
            __floats2half2_rn(a0.x, a0.y), __floats2half2_rn(a0.z, a0.w),
            __floats2half2_rn(a1.x, a1.y), __floats2half2_rn(a1.z, a1.w),
            __floats2half2_rn(a2.x, a2.y), __floats2half2_rn(a2.z, a2.w),
            __floats2half2_rn(a3.x, a3.y), __floats2half2_rn(a3.z, a3.w)};
        *(uint4*)&As[0][am][ak]     = *(uint4*)&ah[0];
        *(uint4*)&As[0][am][ak + 8] = *(uint4*)&ah[4];
        __half2 bh[8] = {
            __floats2half2_rn(b0.x, b0.y), __floats2half2_rn(b0.z, b0.w),
            __floats2half2_rn(b1.x, b1.y), __floats2half2_rn(b1.z, b1.w),
            __floats2half2_rn(b2.x, b2.y), __floats2half2_rn(b2.z, b2.w),
            __floats2half2_rn(b3.x, b3.y), __floats2half2_rn(b3.z, b3.w)};
        *(uint4*)&Bs[0][bk][bn]     = *(uint4*)&bh[0];
        *(uint4*)&Bs[0][bk][bn + 8] = *(uint4*)&bh[4];
    }
    __syncthreads();

    for (int t = 0; t < NT; t++) {
        const int p = t & 1;
        if (t + 1 < NT) {
            int kt = (t + 1) * KT;
            a0 = a1 = a2 = a3 = make_float4(0.f, 0.f, 0.f, 0.f);
            if (gr < N_NODES) {
                const float* xp = &X[(long long)gr * K + kt + ak];
                a0 = *(const float4*)(xp);
                a1 = *(const float4*)(xp + 4);
                a2 = *(const float4*)(xp + 8);
                a3 = *(const float4*)(xp + 12);
            }
            const float* wp = &W[(kt + bk) * HID + bn];
            b0 = *(const float4*)(wp);
            b1 = *(const float4*)(wp + 4);
            b2 = *(const float4*)(wp + 8);
            b3 = *(const float4*)(wp + 12);
        }

#pragma unroll
        for (int ks = 0; ks < KT; ks += 16) {
            wmma::fragment<wmma::matrix_a, 16, 16, 16, __half,
                           wmma::row_major> fa[2];
            wmma::fragment<wmma::matrix_b, 16, 16, 16, __half,
                           wmma::row_major> fb[4];
#pragma unroll
            for (int i = 0; i < 2; i++)
                wmma::load_matrix_sync(fa[i],
                    &As[p][wm * 32 + i * 16][ks], A_LD);
#pragma unroll
            for (int j = 0; j < 4; j++)
                wmma::load_matrix_sync(fb[j],
                    &Bs[p][ks][wn * 64 + j * 16], B_LD);
#pragma unroll
            for (int i = 0; i < 2; i++)
#pragma unroll
                for (int j = 0; j < 4; j++)
                    wmma::mma_sync(fc[i][j], fa[i], fb[j], fc[i][j]);
        }

        if (t + 1 < NT) {
            const int q = p ^ 1;
            __half2 ah[8] = {
                __floats2half2_rn(a0.x, a0.y), __floats2half2_rn(a0.z, a0.w),
                __floats2half2_rn(a1.x, a1.y), __floats2half2_rn(a1.z, a1.w),
                __floats2half2_rn(a2.x, a2.y), __floats2half2_rn(a2.z, a2.w),
                __floats2half2_rn(a3.x, a3.y), __floats2half2_rn(a3.z, a3.w)};
            *(uint4*)&As[q][am][ak]     = *(uint4*)&ah[0];
            *(uint4*)&As[q][am][ak + 8] = *(uint4*)&ah[4];
            __half2 bh[8] = {
                __floats2half2_rn(b0.x, b0.y), __floats2half2_rn(b0.z, b0.w),
                __floats2half2_rn(b1.x, b1.y), __floats2half2_rn(b1.z, b1.w),
                __floats2half2_rn(b2.x, b2.y), __floats2half2_rn(b2.z, b2.w),
                __floats2half2_rn(b3.x, b3.y), __floats2half2_rn(b3.z, b3.w)};
            *(uint4*)&Bs[q][bk][bn]     = *(uint4*)&bh[0];
            *(uint4*)&Bs[q][bk][bn + 8] = *(uint4*)&bh[4];
            __syncthreads();
        }
    }

    const int r  = lane >> 1;
    const int c0 = (lane & 1) * 8;
#pragma unroll
    for (int i = 0; i < 2; i++) {
#pragma unroll
        for (int j = 0; j < 4; j++) {
            wmma::store_matrix_sync(&Cst[wid][0][0], fc[i][j], 20,
                                    wmma::mem_row_major);
            __syncwarp();
            int m = rowBase + wm * 32 + i * 16 + r;
            if (m < N_NODES) {
                int n0 = wn * 64 + j * 16 + c0;
                const float* src = &Cst[wid][r][c0];
                __half2 h[4];
                h[0] = __floats2half2_rn(src[0], src[1]);
                h[1] = __floats2half2_rn(src[2], src[3]);
                h[2] = __floats2half2_rn(src[4], src[5]);
                h[3] = __floats2half2_rn(src[6], src[7]);
                *(uint4*)&g_xw[m * (HID/2) + n0 / 2] = *(uint4*)h;
            }
            __syncwarp();
        }
    }
}

// Fat kernel: blocks [0,391) run GEMM1; blocks [391, 391+3125) run CSR fill.
// GEMM1 depends only on fts/W1; fill depends on the completed scan.
__global__ void __launch_bounds__(256, 2)
k_gemm1_fill(const float* __restrict__ X, const float* __restrict__ W,
             const int* __restrict__ ei) {
    if (blockIdx.x < GEMM_BLOCKS) {
        gemm_body<IN_DIM>(X, W);
    } else {
        int e = (blockIdx.x - GEMM_BLOCKS) * 256 + threadIdx.x;
        if (e < E_EDGES) {
            int s = clampN(ei[e]);
            int d = clampN(ei[E_EDGES + e]);
            int pos = atomicAdd(&g_cur[d], 1);
            g_edge[pos] = make_float2(__int_as_float(s),
                                      g_dinv[s] * g_dinv[d]);
        }
    }
}

__global__ void __launch_bounds__(256, 2)
k_gemm_l2(const float* __restrict__ W) {
    gemm_body<HID>(g_h1, W);
}

// ---------------- agg layer 1: h1 = relu(Ahat @ xw + b1) ------------------
__global__ void __launch_bounds__(256)
k_agg_l1(const float* __restrict__ bias) {
    int w = (blockIdx.x * blockDim.x + threadIdx.x) >> 5;
    if (w >= N_NODES) return;
    int lane = threadIdx.x & 31;

    float di = g_dinv[w];
    float s2 = di * di;

    float4 acc;
    {
        uint2 raw = *(const uint2*)&g_xw[w * (HID/2) + lane * 2];
        float2 f0 = __half22float2(*(__half2*)&raw.x);
        float2 f1 = __half22float2(*(__half2*)&raw.y);
        acc = make_float4(f0.x * s2, f0.y * s2, f1.x * s2, f1.y * s2);
    }

    int beg = g_off[w];
    int end = g_off[w + 1];
    for (int j = beg; j < end; j++) {
        float2 e = __ldg(&g_edge[j]);
        int    s = __float_as_int(e.x);
        float nr = e.y;
        uint2 raw = *(const uint2*)&g_xw[s * (HID/2) + lane * 2];
        float2 f0 = __half22float2(*(__half2*)&raw.x);
        float2 f1 = __half22float2(*(__half2*)&raw.y);
        acc.x += f0.x * nr;
        acc.y += f0.y * nr;
        acc.z += f1.x * nr;
        acc.w += f1.y * nr;
    }

    float4 bb = ((const float4*)bias)[lane];
    acc.x = fmaxf(acc.x + bb.x, 0.f);
    acc.y = fmaxf(acc.y + bb.y, 0.f);
    acc.z = fmaxf(acc.z + bb.z, 0.f);
    acc.w = fmaxf(acc.w + bb.w, 0.f);
    *(float4*)&g_h1[w * HID + lane * 4] = acc;
}

// ---------------- agg layer 2 + fused classifier --------------------------
// x = relu(Ahat @ xw + b2) -> xout; out = x @ Wc + bc (warp-reduced in regs).
__global__ void __launch_bounds__(256)
k_agg_l2_out(const float* __restrict__ bias, float* __restrict__ xout,
             const float* __restrict__ Wc, const float* __restrict__ bc,
             float* __restrict__ out) {
    int w = (blockIdx.x * blockDim.x + threadIdx.x) >> 5;
    if (w >= N_NODES) return;
    int lane = threadIdx.x & 31;

    float di = g_dinv[w];
    float s2 = di * di;

    float4 acc;
    {
        uint2 raw = *(const uint2*)&g_xw[w * (HID/2) + lane * 2];
        float2 f0 = __half22float2(*(__half2*)&raw.x);
        float2 f1 = __half22float2(*(__half2*)&raw.y);
        acc = make_float4(f0.x * s2, f0.y * s2, f1.x * s2, f1.y * s2);
    }

    int beg = g_off[w];
    int end = g_off[w + 1];
    for (int j = beg; j < end; j++) {
        float2 e = __ldg(&g_edge[j]);
        int    s = __float_as_int(e.x);
        float nr = e.y;
        uint2 raw = *(const uint2*)&g_xw[s * (HID/2) + lane * 2];
        float2 f0 = __half22float2(*(__half2*)&raw.x);
        float2 f1 = __half22float2(*(__half2*)&raw.y);
        acc.x += f0.x * nr;
        acc.y += f0.y * nr;
        acc.z += f1.x * nr;
        acc.w += f1.y * nr;
    }

    float4 bb = ((const float4*)bias)[lane];
    acc.x = fmaxf(acc.x + bb.x, 0.f);
    acc.y = fmaxf(acc.y + bb.y, 0.f);
    acc.z = fmaxf(acc.z + bb.z, 0.f);
    acc.w = fmaxf(acc.w + bb.w, 0.f);
    *(float4*)&xout[w * HID + lane * 4] = acc;

    // fused classifier: lane owns channels lane*4 .. lane*4+3
    float av[4] = {acc.x, acc.y, acc.z, acc.w};
    float po[16];
#pragma unroll
    for (int c = 0; c < 16; c++) po[c] = 0.0f;
    const float4* wrow = (const float4*)&Wc[(lane * 4) * OUT_DIM];
#pragma unroll
    for (int i = 0; i < 4; i++) {
#pragma unroll
        for (int c4 = 0; c4 < 4; c4++) {
            float4 wv = __ldg(&wrow[i * 4 + c4]);
            po[c4 * 4 + 0] += av[i] * wv.x;
            po[c4 * 4 + 1] += av[i] * wv.y;
            po[c4 * 4 + 2] += av[i] * wv.z;
            po[c4 * 4 + 3] += av[i] * wv.w;
        }
    }
#pragma unroll
    for (int off = 16; off > 0; off >>= 1)
#pragma unroll
        for (int c = 0; c < 16; c++)
            po[c] += __shfl_xor_sync(0xffffffffu, po[c], off);
    if (lane < OUT_DIM)
        out[w * OUT_DIM + lane] = po[lane] + bc[lane];
}

// ---------------- launch ----------------
extern "C" void kernel_launch(void* const* d_in, const int* in_sizes, int n_in,
                              void* d_out, int out_size) {
    const float* fts = (const float*)d_in[0];
    const int*   ei  = (const int*)d_in[1];
    const float* W1  = (const float*)d_in[2];
    const float* b1  = (const float*)d_in[3];
    const float* W2  = (const float*)d_in[4];
    const float* b2  = (const float*)d_in[5];
    const float* Wc  = (const float*)d_in[6];
    const float* bc  = (const float*)d_in[7];

    float* out  = (float*)d_out;                      // [N, 16]
    float* xout = out + (long long)N_NODES * OUT_DIM; // [N, 128]

    const int TPB = 256;
    const int nodeBlocks = (N_NODES + TPB - 1) / TPB;
    const int edgeBlocks = (E_EDGES + TPB - 1) / TPB;
    const int aggBlocks  = (N_NODES * 32 + TPB - 1) / TPB;

    // CSR prefix chain (cheap), then GEMM1 overlapped with fill
    k_init <<<nodeBlocks, TPB>>>();
    k_count<<<edgeBlocks, TPB>>>(ei);
    k_dinv <<<nodeBlocks, TPB>>>();
    k_scan1<<<SCAN_BLOCKS, SCAN_TPB>>>();
    k_scan2<<<1, SCAN_TPB>>>();
    k_scan3<<<SCAN_BLOCKS, SCAN_TPB>>>();
    k_gemm1_fill<<<GEMM_BLOCKS + FILL_BLOCKS, TPB>>>(fts, W1, ei);

    // layer 1 aggregation
    k_agg_l1<<<aggBlocks, TPB>>>(b1);

    // layer 2 GEMM, then aggregation fused with classifier
    k_gemm_l2   <<<GEMM_BLOCKS, TPB>>>(W2);
    k_agg_l2_out<<<aggBlocks, TPB>>>(b2, xout, Wc, bc, out);
}